// round 4
// baseline (speedup 1.0000x reference)
#include <cuda_runtime.h>
#include <cstdint>
#include <math.h>

#define BATCH 256
#define SEQ 256
#define IN_DIM 128
#define HID 1024
#define OUT_DIM 10
#define KTOT (HID + IN_DIM)   // 1152: [h | x_t] fused A operand

#define BM 32
#define BN 64
#define BK 32
#define APAD 4                // row stride 36 floats = 144B, keeps 16B alignment
#define NTHREADS 256          // 8 warps = 2 per SMSP -> latency hiding

// ping-pong hidden state (2 MB) — __device__ globals are the sanctioned scratch
__device__ float g_h[2][BATCH * HID];

__device__ __forceinline__ void cp_async16(void* smem_dst, const void* gmem_src) {
    unsigned int d = (unsigned int)__cvta_generic_to_shared(smem_dst);
    asm volatile("cp.async.ca.shared.global [%0], [%1], 16;\n" :: "r"(d), "l"(gmem_src));
}
__device__ __forceinline__ void cp_async_commit() {
    asm volatile("cp.async.commit_group;\n");
}
template <int N>
__device__ __forceinline__ void cp_async_wait() {
    asm volatile("cp.async.wait_group %0;\n" :: "n"(N));
}

// One recurrence step: h_out = tanh([h_in | x_t] @ [Whh ; Whx] + bh)
// grid = (HID/BN=16, BATCH/BM=8) = 128 CTAs, 256 threads, 2x4 microtile.
// 2 warps/SMSP: fma-pipe floor unchanged (32 cyc/k) but LDS/bar latency hidden.
__global__ __launch_bounds__(NTHREADS) void rnn_step(
    const float* __restrict__ x,     // [B, S, I]
    const float* __restrict__ Whh,   // [H, H]
    const float* __restrict__ Whx,   // [I, H]
    const float* __restrict__ bh,    // [H]
    int t)
{
    __shared__ float As[2][BM][BK + APAD];
    __shared__ float Bs[2][BK][BN];

    const float* hin  = g_h[t & 1];
    float*       hout = g_h[(t & 1) ^ 1];

    const int bm  = blockIdx.y * BM;
    const int bn  = blockIdx.x * BN;
    const int tid = threadIdx.x;
    const int ty  = tid >> 4;     // 0..15 -> 2 rows each
    const int tx  = tid & 15;     // 0..15 -> 4 cols each

    // t==0: h0 == 0, skip all Whh k-tiles (also avoids reading uninit g_h)
    const int kstart = (t == 0) ? HID : 0;
    const int ntiles = (KTOT - kstart) / BK;

    auto load_tile = [&](int tile, int buf) {
        const int k0 = kstart + tile * BK;
        const float* Asrc;
        long astride;
        if (k0 < HID) { Asrc = hin + k0;                          astride = HID; }
        else          { Asrc = x + (long)t * IN_DIM + (k0 - HID); astride = (long)SEQ * IN_DIM; }
        {   // A tile: 32x32 = 256 float4 slots, 1 per thread
            int m  = tid >> 3;              // 0..31
            int kq = (tid & 7) << 2;        // 0,4,...,28
            cp_async16(&As[buf][m][kq], Asrc + (long)(bm + m) * astride + kq);
        }
        const float* Bsrc = (k0 < HID) ? (Whh + (long)k0 * HID)
                                       : (Whx + (long)(k0 - HID) * HID);
        #pragma unroll
        for (int r = 0; r < 2; r++) {       // B tile: 32x64 = 512 float4 slots
            int idx = tid + r * NTHREADS;
            int kk  = idx >> 4;             // 0..31
            int nq  = (idx & 15) << 2;      // 0,4,...,60
            cp_async16(&Bs[buf][kk][nq], Bsrc + (long)kk * HID + bn + nq);
        }
        cp_async_commit();
    };

    float acc[2][4] = {};

    load_tile(0, 0);

    for (int tile = 0; tile < ntiles; tile++) {
        const int buf = tile & 1;
        if (tile + 1 < ntiles) {
            load_tile(tile + 1, buf ^ 1);
            cp_async_wait<1>();   // group for `tile` complete; tile+1 in flight
        } else {
            cp_async_wait<0>();
        }
        __syncthreads();

        #pragma unroll
        for (int k = 0; k < BK; k++) {
            float4 bv = *(const float4*)&Bs[buf][k][tx << 2];
            float a0 = As[buf][(ty << 1) + 0][k];
            float a1 = As[buf][(ty << 1) + 1][k];
            acc[0][0] = fmaf(a0, bv.x, acc[0][0]); acc[0][1] = fmaf(a0, bv.y, acc[0][1]);
            acc[0][2] = fmaf(a0, bv.z, acc[0][2]); acc[0][3] = fmaf(a0, bv.w, acc[0][3]);
            acc[1][0] = fmaf(a1, bv.x, acc[1][0]); acc[1][1] = fmaf(a1, bv.y, acc[1][1]);
            acc[1][2] = fmaf(a1, bv.z, acc[1][2]); acc[1][3] = fmaf(a1, bv.w, acc[1][3]);
        }
        __syncthreads();
    }

    #pragma unroll
    for (int i = 0; i < 2; i++) {
        int m = bm + (ty << 1) + i;
        float* orow = hout + (long)m * HID;
        #pragma unroll
        for (int j = 0; j < 4; j++) {
            int n = bn + (tx << 2) + j;
            orow[n] = tanhf(acc[i][j] + bh[n]);
        }
    }
}

// Final projection + softmax: out[b,:] = softmax(h_final @ Why + bo)
__global__ __launch_bounds__(128) void rnn_out(
    const float* __restrict__ Why,   // [H, O]
    const float* __restrict__ bo,    // [O]
    float* __restrict__ out)         // [B, O]
{
    const int b   = blockIdx.x;
    const int tid = threadIdx.x;
    const float* h = g_h[0];  // t=255 (odd) writes buf[(1)^1] = buf[0]

    float acc[OUT_DIM];
    #pragma unroll
    for (int o = 0; o < OUT_DIM; o++) acc[o] = 0.0f;

    for (int k = tid; k < HID; k += 128) {
        float hv = h[(long)b * HID + k];
        #pragma unroll
        for (int o = 0; o < OUT_DIM; o++)
            acc[o] = fmaf(hv, Why[k * OUT_DIM + o], acc[o]);
    }

    __shared__ float red[128][OUT_DIM];
    #pragma unroll
    for (int o = 0; o < OUT_DIM; o++) red[tid][o] = acc[o];
    __syncthreads();

    for (int s = 64; s > 0; s >>= 1) {
        if (tid < s) {
            #pragma unroll
            for (int o = 0; o < OUT_DIM; o++) red[tid][o] += red[tid + s][o];
        }
        __syncthreads();
    }

    if (tid == 0) {
        float lg[OUT_DIM];
        float mx = -1e30f;
        #pragma unroll
        for (int o = 0; o < OUT_DIM; o++) {
            lg[o] = red[0][o] + bo[o];
            mx = fmaxf(mx, lg[o]);
        }
        float ssum = 0.0f;
        #pragma unroll
        for (int o = 0; o < OUT_DIM; o++) {
            lg[o] = expf(lg[o] - mx);
            ssum += lg[o];
        }
        float inv = 1.0f / ssum;
        #pragma unroll
        for (int o = 0; o < OUT_DIM; o++)
            out[(long)b * OUT_DIM + o] = lg[o] * inv;
    }
}

extern "C" void kernel_launch(void* const* d_in, const int* in_sizes, int n_in,
                              void* d_out, int out_size) {
    const float* x   = (const float*)d_in[0];
    const float* Whx = (const float*)d_in[1];
    const float* Whh = (const float*)d_in[2];
    const float* bh  = (const float*)d_in[3];
    const float* Why = (const float*)d_in[4];
    const float* bo  = (const float*)d_in[5];
    float* out = (float*)d_out;

    dim3 grid(HID / BN, BATCH / BM);   // (16, 8) = 128 CTAs
    for (int t = 0; t < SEQ; t++)
        rnn_step<<<grid, NTHREADS>>>(x, Whh, Whx, bh, t);
    rnn_out<<<BATCH, 128>>>(Why, bo, out);
}

// round 6
// speedup vs baseline: 1.3871x; 1.3871x over previous
#include <cuda_runtime.h>
#include <cstdint>
#include <math.h>

#define BATCH 256
#define SEQ 256
#define IN_DIM 128
#define HID 1024
#define OUT_DIM 10
#define KTOT 1152            // [h | x_t] fused K
#define BK 32
#define NCHUNK (KTOT / BK)   // 36
#define BM 32
#define BN 64
#define PAD 4
#define LDW (BK + PAD)       // 36 floats row stride

// stage layout (bytes): Ah[32][36] Al[32][36] Bh[64][36] Bl[64][36]
#define OFF_AL 4608
#define OFF_BH 9216
#define OFF_BL 18432
#define STAGE_B 27648
#define DYN_B (2 * STAGE_B)  // 55296 -> needs dynamic smem attribute

// ---- device-global scratch (sanctioned) ----
__device__ float g_hh[2][BATCH * HID];   // hidden hi split (ping-pong)
__device__ float g_hl[2][BATCH * HID];   // hidden lo split
__device__ float g_xh[BATCH * SEQ * IN_DIM];
__device__ float g_xl[BATCH * SEQ * IN_DIM];
__device__ float g_Wh[HID * KTOT];       // W^T [n][k] hi
__device__ float g_Wl[HID * KTOT];       // lo

__device__ __forceinline__ float tf32_rn(float f) {
    unsigned u;
    asm("cvt.rna.tf32.f32 %0, %1;" : "=r"(u) : "f"(f));
    return __uint_as_float(u);
}
__device__ __forceinline__ void cp16(void* smem_dst, const void* g) {
    unsigned d = (unsigned)__cvta_generic_to_shared(smem_dst);
    asm volatile("cp.async.ca.shared.global [%0], [%1], 16;\n" :: "r"(d), "l"(g));
}
__device__ __forceinline__ void cp_commit() { asm volatile("cp.async.commit_group;\n"); }
template <int N>
__device__ __forceinline__ void cp_wait() { asm volatile("cp.async.wait_group %0;\n" :: "n"(N)); }

__device__ __forceinline__ void mma_tf32(float* c, const unsigned* a, unsigned b0, unsigned b1) {
    asm volatile(
        "mma.sync.aligned.m16n8k8.row.col.f32.tf32.tf32.f32 "
        "{%0,%1,%2,%3}, {%4,%5,%6,%7}, {%8,%9}, {%0,%1,%2,%3};"
        : "+f"(c[0]), "+f"(c[1]), "+f"(c[2]), "+f"(c[3])
        : "r"(a[0]), "r"(a[1]), "r"(a[2]), "r"(a[3]), "r"(b0), "r"(b1));
}

// ---- prep: transpose+split W, split x ----
__global__ void split_w(const float* __restrict__ Whh, const float* __restrict__ Whx) {
    int k = blockIdx.x;                          // 0..1151
    for (int n = threadIdx.x; n < HID; n += blockDim.x) {
        float w = (k < HID) ? Whh[(long)k * HID + n] : Whx[(long)(k - HID) * HID + n];
        float hi = tf32_rn(w);
        g_Wh[(long)n * KTOT + k] = hi;
        g_Wl[(long)n * KTOT + k] = tf32_rn(w - hi);
    }
}
__global__ void split_x(const float* __restrict__ x) {
    long i = (long)blockIdx.x * blockDim.x + threadIdx.x;
    if (i < (long)BATCH * SEQ * IN_DIM) {
        float v = x[i];
        float hi = tf32_rn(v);
        g_xh[i] = hi;
        g_xl[i] = tf32_rn(v - hi);
    }
}

// ---- one recurrence step: 3xTF32 on mma.sync tensor path ----
// grid (16, 8) = 128 CTAs, 128 threads (4 warps), warp tile 16x32.
__global__ __launch_bounds__(128, 1) void rnn_step(
    const float* __restrict__ bh, int t)
{
    extern __shared__ char smem[];

    const int tid  = threadIdx.x;
    const int wid  = tid >> 5;
    const int lane = tid & 31;
    const int g    = lane >> 2;     // fragment group 0..7
    const int tg   = lane & 3;      // thread-in-group 0..3
    const int wm   = wid & 1;       // warp m 0..1 (16 rows each)
    const int wn   = wid >> 1;      // warp n 0..1 (32 cols each)

    const int bm = blockIdx.y * BM;
    const int bn = blockIdx.x * BN;

    const float* hh_in = g_hh[t & 1];
    const float* hl_in = g_hl[t & 1];
    float* hh_out = g_hh[(t & 1) ^ 1];
    float* hl_out = g_hl[(t & 1) ^ 1];

    const int kstart = (t == 0) ? HID : 0;      // t==0: h0==0, only x chunks
    const int NC = (KTOT - kstart) / BK;

    auto load_chunk = [&](int ci, int s) {
        const int k0 = kstart + ci * BK;
        char* st = smem + s * STAGE_B;
        float* Ah = (float*)st;
        float* Al = (float*)(st + OFF_AL);
        float* Bh = (float*)(st + OFF_BH);
        float* Bl = (float*)(st + OFF_BL);
        const bool isH = (k0 < HID);
        #pragma unroll
        for (int r = 0; r < 2; r++) {            // A: 32x32 = 256 float4 slots
            int idx = tid + r * 128;
            int m  = idx >> 3;
            int kq = (idx & 7) << 2;
            const float *sh, *sl;
            if (isH) {
                long o = (long)(bm + m) * HID + k0 + kq;
                sh = hh_in + o; sl = hl_in + o;
            } else {
                long o = (long)(bm + m) * (SEQ * IN_DIM) + (long)t * IN_DIM + (k0 - HID) + kq;
                sh = g_xh + o; sl = g_xl + o;
            }
            cp16(&Ah[m * LDW + kq], sh);
            cp16(&Al[m * LDW + kq], sl);
        }
        #pragma unroll
        for (int r = 0; r < 4; r++) {            // B: 64x32 = 512 float4 slots
            int idx = tid + r * 128;
            int n  = idx >> 3;
            int kq = (idx & 7) << 2;
            long o = (long)(bn + n) * KTOT + k0 + kq;
            cp16(&Bh[n * LDW + kq], g_Wh + o);
            cp16(&Bl[n * LDW + kq], g_Wl + o);
        }
        cp_commit();
    };

    float c[4][4] = {};                          // 4 n8-tiles x 4 regs

    load_chunk(0, 0);

    for (int i = 0; i < NC; i++) {
        const int buf = i & 1;
        if (i + 1 < NC) {
            load_chunk(i + 1, buf ^ 1);
            cp_wait<1>();
        } else {
            cp_wait<0>();
        }
        __syncthreads();

        char* st = smem + buf * STAGE_B;
        const unsigned* Ah = (const unsigned*)st;
        const unsigned* Al = (const unsigned*)(st + OFF_AL);
        const unsigned* Bh = (const unsigned*)(st + OFF_BH);
        const unsigned* Bl = (const unsigned*)(st + OFF_BL);

        #pragma unroll
        for (int kb = 0; kb < BK; kb += 8) {
            const int ar0 = (wm * 16 + g) * LDW;
            const int ar1 = ar0 + 8 * LDW;
            unsigned ah[4], al[4];
            ah[0] = Ah[ar0 + kb + tg];     ah[1] = Ah[ar1 + kb + tg];
            ah[2] = Ah[ar0 + kb + tg + 4]; ah[3] = Ah[ar1 + kb + tg + 4];
            al[0] = Al[ar0 + kb + tg];     al[1] = Al[ar1 + kb + tg];
            al[2] = Al[ar0 + kb + tg + 4]; al[3] = Al[ar1 + kb + tg + 4];
            #pragma unroll
            for (int j = 0; j < 4; j++) {
                const int nr = (wn * 32 + j * 8 + g) * LDW;
                unsigned bh0 = Bh[nr + kb + tg], bh1 = Bh[nr + kb + tg + 4];
                unsigned bl0 = Bl[nr + kb + tg], bl1 = Bl[nr + kb + tg + 4];
                mma_tf32(c[j], ah, bh0, bh1);   // Ah*Bh
                mma_tf32(c[j], ah, bl0, bl1);   // Ah*Bl
                mma_tf32(c[j], al, bh0, bh1);   // Al*Bh
            }
        }
        __syncthreads();
    }

    // epilogue: bias + tanh + tf32 hi/lo split, direct from fragments
    #pragma unroll
    for (int j = 0; j < 4; j++) {
        #pragma unroll
        for (int rgi = 0; rgi < 4; rgi++) {
            int row = bm + wm * 16 + g + ((rgi >> 1) << 3);
            int col = bn + wn * 32 + j * 8 + tg * 2 + (rgi & 1);
            float h = tanhf(c[j][rgi] + __ldg(&bh[col]));
            float hi = tf32_rn(h);
            long o = (long)row * HID + col;
            hh_out[o] = hi;
            hl_out[o] = tf32_rn(h - hi);
        }
    }
}

// ---- final projection + softmax ----
__global__ __launch_bounds__(128) void rnn_out(
    const float* __restrict__ Why, const float* __restrict__ bo, float* __restrict__ out)
{
    const int b = blockIdx.x;
    const int tid = threadIdx.x;
    const float* hh = g_hh[0];   // t=255 writes buffer 0
    const float* hl = g_hl[0];

    float acc[OUT_DIM];
    #pragma unroll
    for (int o = 0; o < OUT_DIM; o++) acc[o] = 0.0f;

    for (int k = tid; k < HID; k += 128) {
        float hv = hh[(long)b * HID + k] + hl[(long)b * HID + k];
        #pragma unroll
        for (int o = 0; o < OUT_DIM; o++)
            acc[o] = fmaf(hv, Why[k * OUT_DIM + o], acc[o]);
    }

    __shared__ float red[128][OUT_DIM];
    #pragma unroll
    for (int o = 0; o < OUT_DIM; o++) red[tid][o] = acc[o];
    __syncthreads();
    for (int s = 64; s > 0; s >>= 1) {
        if (tid < s) {
            #pragma unroll
            for (int o = 0; o < OUT_DIM; o++) red[tid][o] += red[tid + s][o];
        }
        __syncthreads();
    }
    if (tid == 0) {
        float lg[OUT_DIM];
        float mx = -1e30f;
        #pragma unroll
        for (int o = 0; o < OUT_DIM; o++) { lg[o] = red[0][o] + bo[o]; mx = fmaxf(mx, lg[o]); }
        float ssum = 0.0f;
        #pragma unroll
        for (int o = 0; o < OUT_DIM; o++) { lg[o] = expf(lg[o] - mx); ssum += lg[o]; }
        float inv = 1.0f / ssum;
        #pragma unroll
        for (int o = 0; o < OUT_DIM; o++) out[(long)b * OUT_DIM + o] = lg[o] * inv;
    }
}

extern "C" void kernel_launch(void* const* d_in, const int* in_sizes, int n_in,
                              void* d_out, int out_size) {
    const float* x   = (const float*)d_in[0];
    const float* Whx = (const float*)d_in[1];
    const float* Whh = (const float*)d_in[2];
    const float* bh  = (const float*)d_in[3];
    const float* Why = (const float*)d_in[4];
    const float* bo  = (const float*)d_in[5];
    float* out = (float*)d_out;

    cudaFuncSetAttribute(rnn_step, cudaFuncAttributeMaxDynamicSharedMemorySize, DYN_B);

    split_w<<<KTOT, 256>>>(Whh, Whx);
    split_x<<<(BATCH * SEQ * IN_DIM) / 256, 256>>>(x);

    dim3 grid(HID / BN, BATCH / BM);   // (16, 8) = 128 CTAs
    for (int t = 0; t < SEQ; t++)
        rnn_step<<<grid, 128, DYN_B>>>(bh, t);
    rnn_out<<<BATCH, 128>>>(Why, bo, out);
}